// round 8
// baseline (speedup 1.0000x reference)
#include <cuda_runtime.h>
#include <math.h>
#include <stdint.h>

// Problem constants
#define Bb 4
#define Ss 2048
#define Ee 1024
#define Hh 512
#define NG 8          // B * 2 heads

// Tile config: 128x64 block tile, BK=16, 256 threads (8 warps: 4 M x 2 N)
#define BM 128
#define BN 64
#define BK 16
#define PADF 8        // row stride ≡ 8 mod 32 banks -> conflict-free frag loads

// Scratch
__device__ float g_Q[NG * Ss * Hh];
__device__ float g_K[NG * Ss * Hh];
__device__ float g_V[NG * Ss * Hh];
__device__ float g_Sc[(size_t)NG * Ss * Ss];
__device__ float g_O[Bb * Ss * Ee];

// fp32 -> tf32 (round-to-nearest) at smem-store time
__device__ __forceinline__ float f2tf32(float x) {
    asm("cvt.rna.tf32.f32 %0, %0;" : "+f"(x));
    return x;
}

// Staging store of a float4 (4 consecutive k values for one column m) into the
// k-transposed tile, with per-thread rotation of the store order so the 4
// lanes sharing the same m hit distinct banks (conflict-free with PADF=8).
#define ST_ROT(arr, lk, m, v, j)                                              \
    do {                                                                      \
        float _c[4] = { f2tf32((v).x), f2tf32((v).y),                         \
                        f2tf32((v).z), f2tf32((v).w) };                       \
        _Pragma("unroll")                                                     \
        for (int _s = 0; _s < 4; _s++) {                                      \
            int _i = ((j) + _s) & 3;                                          \
            arr[(lk) + _i][m] = _c[_i];                                       \
        }                                                                     \
    } while (0)

// Tensor-core compute over one staged tile.
// Requires in scope: wm (0..3), wn (0..1), gid (lane>>2), tig (lane&3),
// float acc[2][4][4].
#define MMA_TILE(AsC, BsC)                                                     \
    _Pragma("unroll")                                                          \
    for (int ks = 0; ks < BK; ks += 8) {                                       \
        uint32_t af[2][4]; uint32_t bf2[4][2];                                 \
        _Pragma("unroll")                                                      \
        for (int mi = 0; mi < 2; mi++) {                                       \
            int mr = wm * 32 + mi * 16 + gid;                                  \
            af[mi][0] = __float_as_uint(AsC[ks + tig][mr]);                    \
            af[mi][1] = __float_as_uint(AsC[ks + tig][mr + 8]);                \
            af[mi][2] = __float_as_uint(AsC[ks + tig + 4][mr]);                \
            af[mi][3] = __float_as_uint(AsC[ks + tig + 4][mr + 8]);            \
        }                                                                      \
        _Pragma("unroll")                                                      \
        for (int ni = 0; ni < 4; ni++) {                                       \
            int nc = wn * 32 + ni * 8 + gid;                                   \
            bf2[ni][0] = __float_as_uint(BsC[ks + tig][nc]);                   \
            bf2[ni][1] = __float_as_uint(BsC[ks + tig + 4][nc]);               \
        }                                                                      \
        _Pragma("unroll")                                                      \
        for (int mi = 0; mi < 2; mi++)                                         \
            _Pragma("unroll")                                                  \
            for (int ni = 0; ni < 4; ni++)                                     \
                asm volatile(                                                  \
                    "mma.sync.aligned.m16n8k8.row.col.f32.tf32.tf32.f32 "      \
                    "{%0,%1,%2,%3}, {%4,%5,%6,%7}, {%8,%9}, {%0,%1,%2,%3};\n"  \
                    : "+f"(acc[mi][ni][0]), "+f"(acc[mi][ni][1]),              \
                      "+f"(acc[mi][ni][2]), "+f"(acc[mi][ni][3])               \
                    : "r"(af[mi][0]), "r"(af[mi][1]),                          \
                      "r"(af[mi][2]), "r"(af[mi][3]),                          \
                      "r"(bf2[ni][0]), "r"(bf2[ni][1]));                       \
    }

// ---------------------------------------------------------------------------
// QKV projection
// ---------------------------------------------------------------------------
__global__ void qkv_kernel(const float* __restrict__ x,
                           const float* __restrict__ Wq, const float* __restrict__ bq,
                           const float* __restrict__ Wk, const float* __restrict__ bk,
                           const float* __restrict__ Wv, const float* __restrict__ bv)
{
    __shared__ float As[2][BK][BM + PADF];
    __shared__ float Bs[2][BK][BN + PADF];

    const int j   = blockIdx.z;
    const int mat = j >> 1;
    const int n   = j & 1;
    const int o0  = blockIdx.x * BN;
    const int m0  = blockIdx.y * BM;

    const float* W    = (mat == 0) ? Wq : (mat == 1) ? Wk : Wv;
    const float* bias = (mat == 0) ? bq : (mat == 1) ? bk : bv;
    float* out        = (mat == 0) ? g_Q : (mat == 1) ? g_K : g_V;

    const float* A  = x + (size_t)m0 * Ee + n * Hh;              // lda = Ee
    const float* Bm = W + (size_t)n * Hh * Hh + (size_t)o0 * Hh; // ldb = Hh

    const int tid = threadIdx.x;
    const int lane = tid & 31;
    const int wm = (tid >> 5) >> 1, wn = (tid >> 5) & 1;
    const int gid = lane >> 2, tig = lane & 3;
    const int lr = tid >> 2, lk = (tid & 3) * 4;
    const int jr = tid & 3;  // store-order rotation

    float acc[2][4][4] = {};

    {
        float4 a0 = *(const float4*)(A + (size_t)lr * Ee + lk);
        float4 a1 = *(const float4*)(A + (size_t)(lr + 64) * Ee + lk);
        float4 b0 = *(const float4*)(Bm + (size_t)lr * Hh + lk);
        ST_ROT(As[0], lk, lr, a0, jr);
        ST_ROT(As[0], lk, lr + 64, a1, jr);
        ST_ROT(Bs[0], lk, lr, b0, jr);
    }
    __syncthreads();

    const int T = Hh / BK;
    int cur = 0;
    for (int t = 0; t < T; t++) {
        float4 pa0, pa1, pb;
        if (t + 1 < T) {
            int k0 = (t + 1) * BK;
            pa0 = *(const float4*)(A + (size_t)lr * Ee + k0 + lk);
            pa1 = *(const float4*)(A + (size_t)(lr + 64) * Ee + k0 + lk);
            pb  = *(const float4*)(Bm + (size_t)lr * Hh + k0 + lk);
        }
        MMA_TILE(As[cur], Bs[cur]);
        if (t + 1 < T) {
            int nx = cur ^ 1;
            ST_ROT(As[nx], lk, lr, pa0, jr);
            ST_ROT(As[nx], lk, lr + 64, pa1, jr);
            ST_ROT(Bs[nx], lk, lr, pb, jr);
            __syncthreads();
            cur = nx;
        }
    }

#pragma unroll
    for (int mi = 0; mi < 2; mi++) {
#pragma unroll
        for (int half = 0; half < 2; half++) {
            int m = m0 + wm * 32 + mi * 16 + gid + half * 8;
            int b = m / Ss, s = m % Ss;
            size_t rowbase = ((size_t)(b * 2 + n) * Ss + s) * Hh;
#pragma unroll
            for (int ni = 0; ni < 4; ni++) {
                int o = o0 + wn * 32 + ni * 8 + tig * 2;
                float c0 = acc[mi][ni][half * 2 + 0] + bias[n * Hh + o];
                float c1 = acc[mi][ni][half * 2 + 1] + bias[n * Hh + o + 1];
                *(float2*)&out[rowbase + o] = make_float2(c0, c1);
            }
        }
    }
}

// ---------------------------------------------------------------------------
// scores: blocks entirely above diagonal skipped (t0 >= s0 + BM)
// ---------------------------------------------------------------------------
__global__ void scores_kernel(const int* __restrict__ maskedp)
{
    __shared__ float As[2][BK][BM + PADF];
    __shared__ float Bs[2][BK][BN + PADF];

    const int g  = blockIdx.z;
    const int t0 = blockIdx.x * BN;
    const int s0 = blockIdx.y * BM;
    const int masked = *maskedp;

    if (masked && t0 >= s0 + BM) return;

    float* out = g_Sc + (size_t)g * Ss * Ss;
    const float* A  = g_Q + (size_t)g * Ss * Hh + (size_t)s0 * Hh;
    const float* Bm = g_K + (size_t)g * Ss * Hh + (size_t)t0 * Hh;

    const int tid = threadIdx.x;
    const int lane = tid & 31;
    const int wm = (tid >> 5) >> 1, wn = (tid >> 5) & 1;
    const int gid = lane >> 2, tig = lane & 3;
    const int lr = tid >> 2, lk = (tid & 3) * 4;
    const int jr = tid & 3;

    float acc[2][4][4] = {};

    {
        float4 a0 = *(const float4*)(A + (size_t)lr * Hh + lk);
        float4 a1 = *(const float4*)(A + (size_t)(lr + 64) * Hh + lk);
        float4 b0 = *(const float4*)(Bm + (size_t)lr * Hh + lk);
        ST_ROT(As[0], lk, lr, a0, jr);
        ST_ROT(As[0], lk, lr + 64, a1, jr);
        ST_ROT(Bs[0], lk, lr, b0, jr);
    }
    __syncthreads();

    const int T = Hh / BK;
    int cur = 0;
    for (int t = 0; t < T; t++) {
        float4 pa0, pa1, pb;
        if (t + 1 < T) {
            int k0 = (t + 1) * BK;
            pa0 = *(const float4*)(A + (size_t)lr * Hh + k0 + lk);
            pa1 = *(const float4*)(A + (size_t)(lr + 64) * Hh + k0 + lk);
            pb  = *(const float4*)(Bm + (size_t)lr * Hh + k0 + lk);
        }
        MMA_TILE(As[cur], Bs[cur]);
        if (t + 1 < T) {
            int nx = cur ^ 1;
            ST_ROT(As[nx], lk, lr, pa0, jr);
            ST_ROT(As[nx], lk, lr + 64, pa1, jr);
            ST_ROT(Bs[nx], lk, lr, pb, jr);
            __syncthreads();
            cur = nx;
        }
    }

    const float scale = 0.044194173824159216f;  // 1/sqrt(512)
#pragma unroll
    for (int mi = 0; mi < 2; mi++) {
#pragma unroll
        for (int half = 0; half < 2; half++) {
            int s = s0 + wm * 32 + mi * 16 + gid + half * 8;
#pragma unroll
            for (int ni = 0; ni < 4; ni++) {
                int tt = t0 + wn * 32 + ni * 8 + tig * 2;
                float c0 = acc[mi][ni][half * 2 + 0] * scale;
                float c1 = acc[mi][ni][half * 2 + 1] * scale;
                if (masked && tt > s)     c0 = -3.0e38f;
                if (masked && tt + 1 > s) c1 = -3.0e38f;
                *(float2*)&out[(size_t)s * Ss + tt] = make_float2(c0, c1);
            }
        }
    }
}

// ---------------------------------------------------------------------------
// Row softmax, causal limit rounded to BM=128 boundary
// ---------------------------------------------------------------------------
__global__ void softmax_kernel(const int* __restrict__ maskedp)
{
    const int row = blockIdx.x;
    const int s = row & (Ss - 1);
    const int limit = (*maskedp) ? (((s >> 7) + 1) << 7) : Ss;

    float* r = g_Sc + (size_t)row * Ss;
    __shared__ float red[8];
    const int tid = threadIdx.x;           // 256 threads
    const int lane = tid & 31, warp = tid >> 5;

    float m = -3.4e38f;
    for (int i = tid; i < limit; i += 256) m = fmaxf(m, r[i]);
#pragma unroll
    for (int off = 16; off > 0; off >>= 1)
        m = fmaxf(m, __shfl_xor_sync(0xFFFFFFFFu, m, off));
    if (lane == 0) red[warp] = m;
    __syncthreads();
    if (warp == 0) {
        float v = (lane < 8) ? red[lane] : -3.4e38f;
#pragma unroll
        for (int off = 4; off > 0; off >>= 1)
            v = fmaxf(v, __shfl_xor_sync(0xFFFFFFFFu, v, off));
        if (lane == 0) red[0] = v;
    }
    __syncthreads();
    m = red[0];
    __syncthreads();

    float sum = 0.f;
    for (int i = tid; i < limit; i += 256) {
        float e = __expf(r[i] - m);
        r[i] = e;
        sum += e;
    }
#pragma unroll
    for (int off = 16; off > 0; off >>= 1)
        sum += __shfl_xor_sync(0xFFFFFFFFu, sum, off);
    if (lane == 0) red[warp] = sum;
    __syncthreads();
    if (warp == 0) {
        float v = (lane < 8) ? red[lane] : 0.f;
#pragma unroll
        for (int off = 4; off > 0; off >>= 1)
            v += __shfl_xor_sync(0xFFFFFFFFu, v, off);
        if (lane == 0) red[0] = v;
    }
    __syncthreads();
    float inv = 1.0f / red[0];
    for (int i = tid; i < limit; i += 256) r[i] *= inv;
}

// ---------------------------------------------------------------------------
// PV: NN GEMM, causal K-limit s0+BM
// ---------------------------------------------------------------------------
__global__ void pv_kernel(const int* __restrict__ maskedp)
{
    __shared__ float As[2][BK][BM + PADF];
    __shared__ float Bs[2][BK][BN + PADF];

    const int g  = blockIdx.z;
    const int h0 = blockIdx.x * BN;
    const int s0 = blockIdx.y * BM;
    const int tid = threadIdx.x;

    const float* A  = g_Sc + (size_t)g * Ss * Ss + (size_t)s0 * Ss;  // lda = Ss
    const float* Bm = g_V + (size_t)g * Ss * Hh;                      // ldb = Hh

    const int kmax = (*maskedp) ? (s0 + BM) : Ss;

    const int lane = tid & 31;
    const int wm = (tid >> 5) >> 1, wn = (tid >> 5) & 1;
    const int gid = lane >> 2, tig = lane & 3;
    const int lr = tid >> 2, lk = (tid & 3) * 4;
    const int jr = tid & 3;
    const int bk = tid >> 4, bn = (tid & 15) * 4;

    float acc[2][4][4] = {};

    {
        float4 a0 = *(const float4*)(A + (size_t)lr * Ss + lk);
        float4 a1 = *(const float4*)(A + (size_t)(lr + 64) * Ss + lk);
        ST_ROT(As[0], lk, lr, a0, jr);
        ST_ROT(As[0], lk, lr + 64, a1, jr);
        float4 b0 = *(const float4*)(Bm + (size_t)bk * Hh + h0 + bn);
        Bs[0][bk][bn+0] = f2tf32(b0.x); Bs[0][bk][bn+1] = f2tf32(b0.y);
        Bs[0][bk][bn+2] = f2tf32(b0.z); Bs[0][bk][bn+3] = f2tf32(b0.w);
    }
    __syncthreads();

    const int T = kmax / BK;
    int cur = 0;
    for (int t = 0; t < T; t++) {
        float4 pa0, pa1, pb;
        if (t + 1 < T) {
            int k0 = (t + 1) * BK;
            pa0 = *(const float4*)(A + (size_t)lr * Ss + k0 + lk);
            pa1 = *(const float4*)(A + (size_t)(lr + 64) * Ss + k0 + lk);
            pb  = *(const float4*)(Bm + (size_t)(k0 + bk) * Hh + h0 + bn);
        }
        MMA_TILE(As[cur], Bs[cur]);
        if (t + 1 < T) {
            int nx = cur ^ 1;
            ST_ROT(As[nx], lk, lr, pa0, jr);
            ST_ROT(As[nx], lk, lr + 64, pa1, jr);
            Bs[nx][bk][bn+0] = f2tf32(pb.x); Bs[nx][bk][bn+1] = f2tf32(pb.y);
            Bs[nx][bk][bn+2] = f2tf32(pb.z); Bs[nx][bk][bn+3] = f2tf32(pb.w);
            __syncthreads();
            cur = nx;
        }
    }

    const int b = g >> 1, n = g & 1;
#pragma unroll
    for (int mi = 0; mi < 2; mi++) {
#pragma unroll
        for (int half = 0; half < 2; half++) {
            int s = s0 + wm * 32 + mi * 16 + gid + half * 8;
            size_t rowbase = ((size_t)b * Ss + s) * Ee + n * Hh;
#pragma unroll
            for (int ni = 0; ni < 4; ni++) {
                int h = h0 + wn * 32 + ni * 8 + tig * 2;
                *(float2*)&g_O[rowbase + h] =
                    make_float2(acc[mi][ni][half * 2 + 0], acc[mi][ni][half * 2 + 1]);
            }
        }
    }
}

// ---------------------------------------------------------------------------
// Final projection (NT) + bias
// ---------------------------------------------------------------------------
__global__ void final_kernel(const float* __restrict__ Wf,
                             const float* __restrict__ bf,
                             float* __restrict__ y)
{
    __shared__ float As[2][BK][BM + PADF];
    __shared__ float Bs[2][BK][BN + PADF];

    const int o0 = blockIdx.x * BN;
    const int m0 = blockIdx.y * BM;
    const int tid = threadIdx.x;

    const float* A  = g_O + (size_t)m0 * Ee;   // lda = Ee
    const float* Bm = Wf + (size_t)o0 * Ee;    // ldb = Ee

    const int lane = tid & 31;
    const int wm = (tid >> 5) >> 1, wn = (tid >> 5) & 1;
    const int gid = lane >> 2, tig = lane & 3;
    const int lr = tid >> 2, lk = (tid & 3) * 4;
    const int jr = tid & 3;

    float acc[2][4][4] = {};

    {
        float4 a0 = *(const float4*)(A + (size_t)lr * Ee + lk);
        float4 a1 = *(const float4*)(A + (size_t)(lr + 64) * Ee + lk);
        float4 b0 = *(const float4*)(Bm + (size_t)lr * Ee + lk);
        ST_ROT(As[0], lk, lr, a0, jr);
        ST_ROT(As[0], lk, lr + 64, a1, jr);
        ST_ROT(Bs[0], lk, lr, b0, jr);
    }
    __syncthreads();

    const int T = Ee / BK;
    int cur = 0;
    for (int t = 0; t < T; t++) {
        float4 pa0, pa1, pb;
        if (t + 1 < T) {
            int k0 = (t + 1) * BK;
            pa0 = *(const float4*)(A + (size_t)lr * Ee + k0 + lk);
            pa1 = *(const float4*)(A + (size_t)(lr + 64) * Ee + k0 + lk);
            pb  = *(const float4*)(Bm + (size_t)lr * Ee + k0 + lk);
        }
        MMA_TILE(As[cur], Bs[cur]);
        if (t + 1 < T) {
            int nx = cur ^ 1;
            ST_ROT(As[nx], lk, lr, pa0, jr);
            ST_ROT(As[nx], lk, lr + 64, pa1, jr);
            ST_ROT(Bs[nx], lk, lr, pb, jr);
            __syncthreads();
            cur = nx;
        }
    }

#pragma unroll
    for (int mi = 0; mi < 2; mi++) {
#pragma unroll
        for (int half = 0; half < 2; half++) {
            int m = m0 + wm * 32 + mi * 16 + gid + half * 8;
#pragma unroll
            for (int ni = 0; ni < 4; ni++) {
                int o = o0 + wn * 32 + ni * 8 + tig * 2;
                float c0 = acc[mi][ni][half * 2 + 0] + bf[o];
                float c1 = acc[mi][ni][half * 2 + 1] + bf[o + 1];
                *(float2*)&y[(size_t)m * Ee + o] = make_float2(c0, c1);
            }
        }
    }
}

// ---------------------------------------------------------------------------
extern "C" void kernel_launch(void* const* d_in, const int* in_sizes, int n_in,
                              void* d_out, int out_size)
{
    const float* x  = (const float*)d_in[0];
    const float* Wq = (const float*)d_in[1];
    const float* bq = (const float*)d_in[2];
    const float* Wk = (const float*)d_in[3];
    const float* bk = (const float*)d_in[4];
    const float* Wv = (const float*)d_in[5];
    const float* bv = (const float*)d_in[6];
    const float* Wf = (const float*)d_in[7];
    const float* bf = (const float*)d_in[8];
    const int* masked = (const int*)d_in[9];
    float* y = (float*)d_out;

    const int M = Bb * Ss;  // 8192 tokens

    qkv_kernel<<<dim3(Hh / BN, M / BM, 6), 256>>>(x, Wq, bq, Wk, bk, Wv, bv);
    scores_kernel<<<dim3(Ss / BN, Ss / BM, NG), 256>>>(masked);
    softmax_kernel<<<NG * Ss, 256>>>(masked);
    pv_kernel<<<dim3(Hh / BN, Ss / BM, NG), 256>>>(masked);
    final_kernel<<<dim3(Ee / BN, M / BM), 256>>>(Wf, bf, y);
}

// round 13
// speedup vs baseline: 1.3257x; 1.3257x over previous
#include <cuda_runtime.h>
#include <math.h>
#include <stdint.h>

// Problem constants
#define Bb 4
#define Ss 2048
#define Ee 1024
#define Hh 512
#define NG 8          // B * 2 heads

// Tile config: 128x64 block tile, BK=16, 256 threads (8 warps: 4 M x 2 N)
#define BM 128
#define BN 64
#define BK 16
#define PADF 4

// Scratch
__device__ float g_Q[NG * Ss * Hh];
__device__ float g_K[NG * Ss * Hh];
__device__ float g_V[NG * Ss * Hh];
__device__ float g_Sc[(size_t)NG * Ss * Ss];
__device__ float g_O[Bb * Ss * Ee];

// fp32 -> tf32 (round-to-nearest) at smem-store time
__device__ __forceinline__ float f2tf32(float x) {
    asm("cvt.rna.tf32.f32 %0, %0;" : "+f"(x));
    return x;
}

// Tensor-core compute over one staged tile.
// Requires in scope: wm (0..3), wn (0..1), gid (lane>>2), tig (lane&3),
// float acc[2][4][4].
#define MMA_TILE(AsC, BsC)                                                     \
    _Pragma("unroll")                                                          \
    for (int ks = 0; ks < BK; ks += 8) {                                       \
        uint32_t af[2][4]; uint32_t bf2[4][2];                                 \
        _Pragma("unroll")                                                      \
        for (int mi = 0; mi < 2; mi++) {                                       \
            int mr = wm * 32 + mi * 16 + gid;                                  \
            af[mi][0] = __float_as_uint(AsC[ks + tig][mr]);                    \
            af[mi][1] = __float_as_uint(AsC[ks + tig][mr + 8]);                \
            af[mi][2] = __float_as_uint(AsC[ks + tig + 4][mr]);                \
            af[mi][3] = __float_as_uint(AsC[ks + tig + 4][mr + 8]);            \
        }                                                                      \
        _Pragma("unroll")                                                      \
        for (int ni = 0; ni < 4; ni++) {                                       \
            int nc = wn * 32 + ni * 8 + gid;                                   \
            bf2[ni][0] = __float_as_uint(BsC[ks + tig][nc]);                   \
            bf2[ni][1] = __float_as_uint(BsC[ks + tig + 4][nc]);               \
        }                                                                      \
        _Pragma("unroll")                                                      \
        for (int mi = 0; mi < 2; mi++)                                         \
            _Pragma("unroll")                                                  \
            for (int ni = 0; ni < 4; ni++)                                     \
                asm volatile(                                                  \
                    "mma.sync.aligned.m16n8k8.row.col.f32.tf32.tf32.f32 "      \
                    "{%0,%1,%2,%3}, {%4,%5,%6,%7}, {%8,%9}, {%0,%1,%2,%3};\n"  \
                    : "+f"(acc[mi][ni][0]), "+f"(acc[mi][ni][1]),              \
                      "+f"(acc[mi][ni][2]), "+f"(acc[mi][ni][3])               \
                    : "r"(af[mi][0]), "r"(af[mi][1]),                          \
                      "r"(af[mi][2]), "r"(af[mi][3]),                          \
                      "r"(bf2[ni][0]), "r"(bf2[ni][1]));                       \
    }

// ---------------------------------------------------------------------------
// QKV projection
// ---------------------------------------------------------------------------
__global__ void qkv_kernel(const float* __restrict__ x,
                           const float* __restrict__ Wq, const float* __restrict__ bq,
                           const float* __restrict__ Wk, const float* __restrict__ bk,
                           const float* __restrict__ Wv, const float* __restrict__ bv)
{
    __shared__ float As[2][BK][BM + PADF];
    __shared__ float Bs[2][BK][BN + PADF];

    const int j   = blockIdx.z;
    const int mat = j >> 1;
    const int n   = j & 1;
    const int o0  = blockIdx.x * BN;
    const int m0  = blockIdx.y * BM;

    const float* W    = (mat == 0) ? Wq : (mat == 1) ? Wk : Wv;
    const float* bias = (mat == 0) ? bq : (mat == 1) ? bk : bv;
    float* out        = (mat == 0) ? g_Q : (mat == 1) ? g_K : g_V;

    const float* A  = x + (size_t)m0 * Ee + n * Hh;              // lda = Ee
    const float* Bm = W + (size_t)n * Hh * Hh + (size_t)o0 * Hh; // ldb = Hh

    const int tid = threadIdx.x;
    const int lane = tid & 31;
    const int wm = (tid >> 5) >> 1, wn = (tid >> 5) & 1;
    const int gid = lane >> 2, tig = lane & 3;
    const int lr = tid >> 2, lk = (tid & 3) * 4;

    float acc[2][4][4] = {};

    {
        float4 a0 = *(const float4*)(A + (size_t)lr * Ee + lk);
        float4 a1 = *(const float4*)(A + (size_t)(lr + 64) * Ee + lk);
        float4 b0 = *(const float4*)(Bm + (size_t)lr * Hh + lk);
        As[0][lk+0][lr] = f2tf32(a0.x); As[0][lk+1][lr] = f2tf32(a0.y); As[0][lk+2][lr] = f2tf32(a0.z); As[0][lk+3][lr] = f2tf32(a0.w);
        As[0][lk+0][lr+64] = f2tf32(a1.x); As[0][lk+1][lr+64] = f2tf32(a1.y); As[0][lk+2][lr+64] = f2tf32(a1.z); As[0][lk+3][lr+64] = f2tf32(a1.w);
        Bs[0][lk+0][lr] = f2tf32(b0.x); Bs[0][lk+1][lr] = f2tf32(b0.y); Bs[0][lk+2][lr] = f2tf32(b0.z); Bs[0][lk+3][lr] = f2tf32(b0.w);
    }
    __syncthreads();

    const int T = Hh / BK;
    int cur = 0;
    for (int t = 0; t < T; t++) {
        float4 pa0, pa1, pb;
        if (t + 1 < T) {
            int k0 = (t + 1) * BK;
            pa0 = *(const float4*)(A + (size_t)lr * Ee + k0 + lk);
            pa1 = *(const float4*)(A + (size_t)(lr + 64) * Ee + k0 + lk);
            pb  = *(const float4*)(Bm + (size_t)lr * Hh + k0 + lk);
        }
        MMA_TILE(As[cur], Bs[cur]);
        if (t + 1 < T) {
            int nx = cur ^ 1;
            As[nx][lk+0][lr] = f2tf32(pa0.x); As[nx][lk+1][lr] = f2tf32(pa0.y); As[nx][lk+2][lr] = f2tf32(pa0.z); As[nx][lk+3][lr] = f2tf32(pa0.w);
            As[nx][lk+0][lr+64] = f2tf32(pa1.x); As[nx][lk+1][lr+64] = f2tf32(pa1.y); As[nx][lk+2][lr+64] = f2tf32(pa1.z); As[nx][lk+3][lr+64] = f2tf32(pa1.w);
            Bs[nx][lk+0][lr] = f2tf32(pb.x); Bs[nx][lk+1][lr] = f2tf32(pb.y); Bs[nx][lk+2][lr] = f2tf32(pb.z); Bs[nx][lk+3][lr] = f2tf32(pb.w);
            __syncthreads();
            cur = nx;
        }
    }

#pragma unroll
    for (int mi = 0; mi < 2; mi++) {
#pragma unroll
        for (int half = 0; half < 2; half++) {
            int m = m0 + wm * 32 + mi * 16 + gid + half * 8;
            int b = m / Ss, s = m % Ss;
            size_t rowbase = ((size_t)(b * 2 + n) * Ss + s) * Hh;
#pragma unroll
            for (int ni = 0; ni < 4; ni++) {
                int o = o0 + wn * 32 + ni * 8 + tig * 2;
                float c0 = acc[mi][ni][half * 2 + 0] + bias[n * Hh + o];
                float c1 = acc[mi][ni][half * 2 + 1] + bias[n * Hh + o + 1];
                *(float2*)&out[rowbase + o] = make_float2(c0, c1);
            }
        }
    }
}

// ---------------------------------------------------------------------------
// scores: blocks entirely above diagonal skipped (t0 >= s0 + BM).
// Longest-first: s0 descends as blockIdx.y ascends, so expensive CTAs launch
// in the first waves and the tail wave holds only cheap/empty blocks.
// ---------------------------------------------------------------------------
__global__ void scores_kernel(const int* __restrict__ maskedp)
{
    __shared__ float As[2][BK][BM + PADF];
    __shared__ float Bs[2][BK][BN + PADF];

    const int g  = blockIdx.z;
    const int t0 = blockIdx.x * BN;
    const int s0 = (gridDim.y - 1 - blockIdx.y) * BM;   // reversed order
    const int masked = *maskedp;

    if (masked && t0 >= s0 + BM) return;

    float* out = g_Sc + (size_t)g * Ss * Ss;
    const float* A  = g_Q + (size_t)g * Ss * Hh + (size_t)s0 * Hh;
    const float* Bm = g_K + (size_t)g * Ss * Hh + (size_t)t0 * Hh;

    const int tid = threadIdx.x;
    const int lane = tid & 31;
    const int wm = (tid >> 5) >> 1, wn = (tid >> 5) & 1;
    const int gid = lane >> 2, tig = lane & 3;
    const int lr = tid >> 2, lk = (tid & 3) * 4;

    float acc[2][4][4] = {};

    {
        float4 a0 = *(const float4*)(A + (size_t)lr * Hh + lk);
        float4 a1 = *(const float4*)(A + (size_t)(lr + 64) * Hh + lk);
        float4 b0 = *(const float4*)(Bm + (size_t)lr * Hh + lk);
        As[0][lk+0][lr] = f2tf32(a0.x); As[0][lk+1][lr] = f2tf32(a0.y); As[0][lk+2][lr] = f2tf32(a0.z); As[0][lk+3][lr] = f2tf32(a0.w);
        As[0][lk+0][lr+64] = f2tf32(a1.x); As[0][lk+1][lr+64] = f2tf32(a1.y); As[0][lk+2][lr+64] = f2tf32(a1.z); As[0][lk+3][lr+64] = f2tf32(a1.w);
        Bs[0][lk+0][lr] = f2tf32(b0.x); Bs[0][lk+1][lr] = f2tf32(b0.y); Bs[0][lk+2][lr] = f2tf32(b0.z); Bs[0][lk+3][lr] = f2tf32(b0.w);
    }
    __syncthreads();

    const int T = Hh / BK;
    int cur = 0;
    for (int t = 0; t < T; t++) {
        float4 pa0, pa1, pb;
        if (t + 1 < T) {
            int k0 = (t + 1) * BK;
            pa0 = *(const float4*)(A + (size_t)lr * Hh + k0 + lk);
            pa1 = *(const float4*)(A + (size_t)(lr + 64) * Hh + k0 + lk);
            pb  = *(const float4*)(Bm + (size_t)lr * Hh + k0 + lk);
        }
        MMA_TILE(As[cur], Bs[cur]);
        if (t + 1 < T) {
            int nx = cur ^ 1;
            As[nx][lk+0][lr] = f2tf32(pa0.x); As[nx][lk+1][lr] = f2tf32(pa0.y); As[nx][lk+2][lr] = f2tf32(pa0.z); As[nx][lk+3][lr] = f2tf32(pa0.w);
            As[nx][lk+0][lr+64] = f2tf32(pa1.x); As[nx][lk+1][lr+64] = f2tf32(pa1.y); As[nx][lk+2][lr+64] = f2tf32(pa1.z); As[nx][lk+3][lr+64] = f2tf32(pa1.w);
            Bs[nx][lk+0][lr] = f2tf32(pb.x); Bs[nx][lk+1][lr] = f2tf32(pb.y); Bs[nx][lk+2][lr] = f2tf32(pb.z); Bs[nx][lk+3][lr] = f2tf32(pb.w);
            __syncthreads();
            cur = nx;
        }
    }

    const float scale = 0.044194173824159216f;  // 1/sqrt(512)
#pragma unroll
    for (int mi = 0; mi < 2; mi++) {
#pragma unroll
        for (int half = 0; half < 2; half++) {
            int s = s0 + wm * 32 + mi * 16 + gid + half * 8;
#pragma unroll
            for (int ni = 0; ni < 4; ni++) {
                int tt = t0 + wn * 32 + ni * 8 + tig * 2;
                float c0 = acc[mi][ni][half * 2 + 0] * scale;
                float c1 = acc[mi][ni][half * 2 + 1] * scale;
                if (masked && tt > s)     c0 = -3.0e38f;
                if (masked && tt + 1 > s) c1 = -3.0e38f;
                *(float2*)&out[(size_t)s * Ss + tt] = make_float2(c0, c1);
            }
        }
    }
}

// ---------------------------------------------------------------------------
// Row softmax, causal limit rounded to BM=128 boundary.
// Longest rows first; float4-vectorized (limit is always a multiple of 128).
// ---------------------------------------------------------------------------
__global__ void softmax_kernel(const int* __restrict__ maskedp)
{
    const int row0 = gridDim.x - 1 - blockIdx.x;   // reversed: big s first
    const int s = row0 & (Ss - 1);
    const int limit = (*maskedp) ? (((s >> 7) + 1) << 7) : Ss;
    const int nvec = limit >> 2;                   // float4 count (multiple of 32)

    float4* r4 = (float4*)(g_Sc + (size_t)row0 * Ss);
    __shared__ float red[8];
    const int tid = threadIdx.x;           // 256 threads
    const int lane = tid & 31, warp = tid >> 5;

    float m = -3.4e38f;
    for (int i = tid; i < nvec; i += 256) {
        float4 v = r4[i];
        m = fmaxf(m, fmaxf(fmaxf(v.x, v.y), fmaxf(v.z, v.w)));
    }
#pragma unroll
    for (int off = 16; off > 0; off >>= 1)
        m = fmaxf(m, __shfl_xor_sync(0xFFFFFFFFu, m, off));
    if (lane == 0) red[warp] = m;
    __syncthreads();
    if (warp == 0) {
        float v = (lane < 8) ? red[lane] : -3.4e38f;
#pragma unroll
        for (int off = 4; off > 0; off >>= 1)
            v = fmaxf(v, __shfl_xor_sync(0xFFFFFFFFu, v, off));
        if (lane == 0) red[0] = v;
    }
    __syncthreads();
    m = red[0];
    __syncthreads();

    float sum = 0.f;
    for (int i = tid; i < nvec; i += 256) {
        float4 v = r4[i];
        v.x = __expf(v.x - m); v.y = __expf(v.y - m);
        v.z = __expf(v.z - m); v.w = __expf(v.w - m);
        r4[i] = v;
        sum += (v.x + v.y) + (v.z + v.w);
    }
#pragma unroll
    for (int off = 16; off > 0; off >>= 1)
        sum += __shfl_xor_sync(0xFFFFFFFFu, sum, off);
    if (lane == 0) red[warp] = sum;
    __syncthreads();
    if (warp == 0) {
        float v = (lane < 8) ? red[lane] : 0.f;
#pragma unroll
        for (int off = 4; off > 0; off >>= 1)
            v += __shfl_xor_sync(0xFFFFFFFFu, v, off);
        if (lane == 0) red[0] = v;
    }
    __syncthreads();
    float inv = 1.0f / red[0];
    for (int i = tid; i < nvec; i += 256) {
        float4 v = r4[i];
        v.x *= inv; v.y *= inv; v.z *= inv; v.w *= inv;
        r4[i] = v;
    }
}

// ---------------------------------------------------------------------------
// PV: NN GEMM, causal K-limit s0+BM. Longest-first CTA order (s0 reversed):
// the 16x work-variance across s0 otherwise leaves the longest CTAs in the
// final wave, draining the chip (measured occ 32%).
// ---------------------------------------------------------------------------
__global__ void pv_kernel(const int* __restrict__ maskedp)
{
    __shared__ float As[2][BK][BM + PADF];
    __shared__ float Bs[2][BK][BN + PADF];

    const int g  = blockIdx.z;
    const int h0 = blockIdx.x * BN;
    const int s0 = (gridDim.y - 1 - blockIdx.y) * BM;   // reversed order
    const int tid = threadIdx.x;

    const float* A  = g_Sc + (size_t)g * Ss * Ss + (size_t)s0 * Ss;  // lda = Ss
    const float* Bm = g_V + (size_t)g * Ss * Hh;                      // ldb = Hh

    const int kmax = (*maskedp) ? (s0 + BM) : Ss;

    const int lane = tid & 31;
    const int wm = (tid >> 5) >> 1, wn = (tid >> 5) & 1;
    const int gid = lane >> 2, tig = lane & 3;
    const int lr = tid >> 2, lk = (tid & 3) * 4;
    const int bk = tid >> 4, bn = (tid & 15) * 4;

    float acc[2][4][4] = {};

    {
        float4 a0 = *(const float4*)(A + (size_t)lr * Ss + lk);
        float4 a1 = *(const float4*)(A + (size_t)(lr + 64) * Ss + lk);
        As[0][lk+0][lr] = f2tf32(a0.x); As[0][lk+1][lr] = f2tf32(a0.y); As[0][lk+2][lr] = f2tf32(a0.z); As[0][lk+3][lr] = f2tf32(a0.w);
        As[0][lk+0][lr+64] = f2tf32(a1.x); As[0][lk+1][lr+64] = f2tf32(a1.y); As[0][lk+2][lr+64] = f2tf32(a1.z); As[0][lk+3][lr+64] = f2tf32(a1.w);
        float4 b0 = *(const float4*)(Bm + (size_t)bk * Hh + h0 + bn);
        Bs[0][bk][bn+0] = f2tf32(b0.x); Bs[0][bk][bn+1] = f2tf32(b0.y);
        Bs[0][bk][bn+2] = f2tf32(b0.z); Bs[0][bk][bn+3] = f2tf32(b0.w);
    }
    __syncthreads();

    const int T = kmax / BK;
    int cur = 0;
    for (int t = 0; t < T; t++) {
        float4 pa0, pa1, pb;
        if (t + 1 < T) {
            int k0 = (t + 1) * BK;
            pa0 = *(const float4*)(A + (size_t)lr * Ss + k0 + lk);
            pa1 = *(const float4*)(A + (size_t)(lr + 64) * Ss + k0 + lk);
            pb  = *(const float4*)(Bm + (size_t)(k0 + bk) * Hh + h0 + bn);
        }
        MMA_TILE(As[cur], Bs[cur]);
        if (t + 1 < T) {
            int nx = cur ^ 1;
            As[nx][lk+0][lr] = f2tf32(pa0.x); As[nx][lk+1][lr] = f2tf32(pa0.y); As[nx][lk+2][lr] = f2tf32(pa0.z); As[nx][lk+3][lr] = f2tf32(pa0.w);
            As[nx][lk+0][lr+64] = f2tf32(pa1.x); As[nx][lk+1][lr+64] = f2tf32(pa1.y); As[nx][lk+2][lr+64] = f2tf32(pa1.z); As[nx][lk+3][lr+64] = f2tf32(pa1.w);
            Bs[nx][bk][bn+0] = f2tf32(pb.x); Bs[nx][bk][bn+1] = f2tf32(pb.y);
            Bs[nx][bk][bn+2] = f2tf32(pb.z); Bs[nx][bk][bn+3] = f2tf32(pb.w);
            __syncthreads();
            cur = nx;
        }
    }

    const int b = g >> 1, n = g & 1;
#pragma unroll
    for (int mi = 0; mi < 2; mi++) {
#pragma unroll
        for (int half = 0; half < 2; half++) {
            int s = s0 + wm * 32 + mi * 16 + gid + half * 8;
            size_t rowbase = ((size_t)b * Ss + s) * Ee + n * Hh;
#pragma unroll
            for (int ni = 0; ni < 4; ni++) {
                int h = h0 + wn * 32 + ni * 8 + tig * 2;
                *(float2*)&g_O[rowbase + h] =
                    make_float2(acc[mi][ni][half * 2 + 0], acc[mi][ni][half * 2 + 1]);
            }
        }
    }
}

// ---------------------------------------------------------------------------
// Final projection (NT) + bias
// ---------------------------------------------------------------------------
__global__ void final_kernel(const float* __restrict__ Wf,
                             const float* __restrict__ bf,
                             float* __restrict__ y)
{
    __shared__ float As[2][BK][BM + PADF];
    __shared__ float Bs[2][BK][BN + PADF];

    const int o0 = blockIdx.x * BN;
    const int m0 = blockIdx.y * BM;
    const int tid = threadIdx.x;

    const float* A  = g_O + (size_t)m0 * Ee;   // lda = Ee
    const float* Bm = Wf + (size_t)o0 * Ee;    // ldb = Ee

    const int lane = tid & 31;
    const int wm = (tid >> 5) >> 1, wn = (tid >> 5) & 1;
    const int gid = lane >> 2, tig = lane & 3;
    const int lr = tid >> 2, lk = (tid & 3) * 4;

    float acc[2][4][4] = {};

    {
        float4 a0 = *(const float4*)(A + (size_t)lr * Ee + lk);
        float4 a1 = *(const float4*)(A + (size_t)(lr + 64) * Ee + lk);
        float4 b0 = *(const float4*)(Bm + (size_t)lr * Ee + lk);
        As[0][lk+0][lr] = f2tf32(a0.x); As[0][lk+1][lr] = f2tf32(a0.y); As[0][lk+2][lr] = f2tf32(a0.z); As[0][lk+3][lr] = f2tf32(a0.w);
        As[0][lk+0][lr+64] = f2tf32(a1.x); As[0][lk+1][lr+64] = f2tf32(a1.y); As[0][lk+2][lr+64] = f2tf32(a1.z); As[0][lk+3][lr+64] = f2tf32(a1.w);
        Bs[0][lk+0][lr] = f2tf32(b0.x); Bs[0][lk+1][lr] = f2tf32(b0.y); Bs[0][lk+2][lr] = f2tf32(b0.z); Bs[0][lk+3][lr] = f2tf32(b0.w);
    }
    __syncthreads();

    const int T = Ee / BK;
    int cur = 0;
    for (int t = 0; t < T; t++) {
        float4 pa0, pa1, pb;
        if (t + 1 < T) {
            int k0 = (t + 1) * BK;
            pa0 = *(const float4*)(A + (size_t)lr * Ee + k0 + lk);
            pa1 = *(const float4*)(A + (size_t)(lr + 64) * Ee + k0 + lk);
            pb  = *(const float4*)(Bm + (size_t)lr * Ee + k0 + lk);
        }
        MMA_TILE(As[cur], Bs[cur]);
        if (t + 1 < T) {
            int nx = cur ^ 1;
            As[nx][lk+0][lr] = f2tf32(pa0.x); As[nx][lk+1][lr] = f2tf32(pa0.y); As[nx][lk+2][lr] = f2tf32(pa0.z); As[nx][lk+3][lr] = f2tf32(pa0.w);
            As[nx][lk+0][lr+64] = f2tf32(pa1.x); As[nx][lk+1][lr+64] = f2tf32(pa1.y); As[nx][lk+2][lr+64] = f2tf32(pa1.z); As[nx][lk+3][lr+64] = f2tf32(pa1.w);
            Bs[nx][lk+0][lr] = f2tf32(pb.x); Bs[nx][lk+1][lr] = f2tf32(pb.y); Bs[nx][lk+2][lr] = f2tf32(pb.z); Bs[nx][lk+3][lr] = f2tf32(pb.w);
            __syncthreads();
            cur = nx;
        }
    }

#pragma unroll
    for (int mi = 0; mi < 2; mi++) {
#pragma unroll
        for (int half = 0; half < 2; half++) {
            int m = m0 + wm * 32 + mi * 16 + gid + half * 8;
#pragma unroll
            for (int ni = 0; ni < 4; ni++) {
                int o = o0 + wn * 32 + ni * 8 + tig * 2;
                float c0 = acc[mi][ni][half * 2 + 0] + bf[o];
                float c1 = acc[mi][ni][half * 2 + 1] + bf[o + 1];
                *(float2*)&y[(size_t)m * Ee + o] = make_float2(c0, c1);
            }
        }
    }
}

// ---------------------------------------------------------------------------
extern "C" void kernel_launch(void* const* d_in, const int* in_sizes, int n_in,
                              void* d_out, int out_size)
{
    const float* x  = (const float*)d_in[0];
    const float* Wq = (const float*)d_in[1];
    const float* bq = (const float*)d_in[2];
    const float* Wk = (const float*)d_in[3];
    const float* bk = (const float*)d_in[4];
    const float* Wv = (const float*)d_in[5];
    const float* bv = (const float*)d_in[6];
    const float* Wf = (const float*)d_in[7];
    const float* bf = (const float*)d_in[8];
    const int* masked = (const int*)d_in[9];
    float* y = (float*)d_out;

    const int M = Bb * Ss;  // 8192 tokens

    qkv_kernel<<<dim3(Hh / BN, M / BM, 6), 256>>>(x, Wq, bq, Wk, bk, Wv, bv);
    scores_kernel<<<dim3(Ss / BN, Ss / BM, NG), 256>>>(masked);
    softmax_kernel<<<NG * Ss, 256>>>(masked);
    pv_kernel<<<dim3(Hh / BN, Ss / BM, NG), 256>>>(masked);
    final_kernel<<<dim3(Ee / BN, M / BM), 256>>>(Wf, bf, y);
}

// round 15
// speedup vs baseline: 1.4987x; 1.1305x over previous
#include <cuda_runtime.h>
#include <math.h>
#include <stdint.h>

// Problem constants
#define Bb 4
#define Ss 2048
#define Ee 1024
#define Hh 512
#define NG 8          // B * 2 heads

// Tile config: 128x64 block tile, BK=16, 256 threads (8 warps: 4 M x 2 N)
#define BM 128
#define BN 64
#define BK 16
#define PADF 4        // pad for [BK][N] layouts (qkv/final staging, pv B tile)
#define PADK 4        // pad for k-contiguous [M][BK+PADK] cp.async tiles (stride 20)
#define NSTG 3        // cp.async pipeline stages

// Scratch
__device__ float g_Q[NG * Ss * Hh];
__device__ float g_K[NG * Ss * Hh];
__device__ float g_V[NG * Ss * Hh];
__device__ float g_Sc[(size_t)NG * Ss * Ss];
__device__ float g_O[Bb * Ss * Ee];

// fp32 -> tf32 (round-to-nearest)
__device__ __forceinline__ float f2tf32(float x) {
    asm("cvt.rna.tf32.f32 %0, %0;" : "+f"(x));
    return x;
}

// cp.async helpers
__device__ __forceinline__ void cp16(void* dst, const void* src) {
    uint32_t d = (uint32_t)__cvta_generic_to_shared(dst);
    asm volatile("cp.async.cg.shared.global [%0], [%1], 16;\n" :: "r"(d), "l"(src));
}
__device__ __forceinline__ void cp_commit() {
    asm volatile("cp.async.commit_group;\n" ::: "memory");
}
__device__ __forceinline__ void cp_wait_1() {
    asm volatile("cp.async.wait_group 1;\n" ::: "memory");
}

// --- MMA over k-transposed staged tiles (qkv/final: As[BK][BM], Bs[BK][BN]) ---
#define MMA_TILE(AsC, BsC)                                                     \
    _Pragma("unroll")                                                          \
    for (int ks = 0; ks < BK; ks += 8) {                                       \
        uint32_t af[2][4]; uint32_t bf2[4][2];                                 \
        _Pragma("unroll")                                                      \
        for (int mi = 0; mi < 2; mi++) {                                       \
            int mr = wm * 32 + mi * 16 + gid;                                  \
            af[mi][0] = __float_as_uint(AsC[ks + tig][mr]);                    \
            af[mi][1] = __float_as_uint(AsC[ks + tig][mr + 8]);                \
            af[mi][2] = __float_as_uint(AsC[ks + tig + 4][mr]);                \
            af[mi][3] = __float_as_uint(AsC[ks + tig + 4][mr + 8]);            \
        }                                                                      \
        _Pragma("unroll")                                                      \
        for (int ni = 0; ni < 4; ni++) {                                       \
            int nc = wn * 32 + ni * 8 + gid;                                   \
            bf2[ni][0] = __float_as_uint(BsC[ks + tig][nc]);                   \
            bf2[ni][1] = __float_as_uint(BsC[ks + tig + 4][nc]);               \
        }                                                                      \
        _Pragma("unroll")                                                      \
        for (int mi = 0; mi < 2; mi++)                                         \
            _Pragma("unroll")                                                  \
            for (int ni = 0; ni < 4; ni++)                                     \
                asm volatile(                                                  \
                    "mma.sync.aligned.m16n8k8.row.col.f32.tf32.tf32.f32 "      \
                    "{%0,%1,%2,%3}, {%4,%5,%6,%7}, {%8,%9}, {%0,%1,%2,%3};\n"  \
                    : "+f"(acc[mi][ni][0]), "+f"(acc[mi][ni][1]),              \
                      "+f"(acc[mi][ni][2]), "+f"(acc[mi][ni][3])               \
                    : "r"(af[mi][0]), "r"(af[mi][1]),                          \
                      "r"(af[mi][2]), "r"(af[mi][3]),                          \
                      "r"(bf2[ni][0]), "r"(bf2[ni][1]));                       \
    }

// --- MMA, both operands k-contiguous (scores: As[BM][BK+PADK], Bs[BN][BK+PADK]) ---
#define MMA_KK(AsC, BsC)                                                       \
    _Pragma("unroll")                                                          \
    for (int ks = 0; ks < BK; ks += 8) {                                       \
        uint32_t af[2][4]; uint32_t bf2[4][2];                                 \
        _Pragma("unroll")                                                      \
        for (int mi = 0; mi < 2; mi++) {                                       \
            int mr = wm * 32 + mi * 16 + gid;                                  \
            af[mi][0] = __float_as_uint(AsC[mr][ks + tig]);                    \
            af[mi][1] = __float_as_uint(AsC[mr + 8][ks + tig]);                \
            af[mi][2] = __float_as_uint(AsC[mr][ks + tig + 4]);                \
            af[mi][3] = __float_as_uint(AsC[mr + 8][ks + tig + 4]);            \
        }                                                                      \
        _Pragma("unroll")                                                      \
        for (int ni = 0; ni < 4; ni++) {                                       \
            int nc = wn * 32 + ni * 8 + gid;                                   \
            bf2[ni][0] = __float_as_uint(BsC[nc][ks + tig]);                   \
            bf2[ni][1] = __float_as_uint(BsC[nc][ks + tig + 4]);               \
        }                                                                      \
        _Pragma("unroll")                                                      \
        for (int mi = 0; mi < 2; mi++)                                         \
            _Pragma("unroll")                                                  \
            for (int ni = 0; ni < 4; ni++)                                     \
                asm volatile(                                                  \
                    "mma.sync.aligned.m16n8k8.row.col.f32.tf32.tf32.f32 "      \
                    "{%0,%1,%2,%3}, {%4,%5,%6,%7}, {%8,%9}, {%0,%1,%2,%3};\n"  \
                    : "+f"(acc[mi][ni][0]), "+f"(acc[mi][ni][1]),              \
                      "+f"(acc[mi][ni][2]), "+f"(acc[mi][ni][3])               \
                    : "r"(af[mi][0]), "r"(af[mi][1]),                          \
                      "r"(af[mi][2]), "r"(af[mi][3]),                          \
                      "r"(bf2[ni][0]), "r"(bf2[ni][1]));                       \
    }

// --- MMA, A k-contiguous, B n-contiguous (pv: As[BM][BK+PADK], Bs[BK][BN+PADF]) ---
#define MMA_KN(AsC, BsC)                                                       \
    _Pragma("unroll")                                                          \
    for (int ks = 0; ks < BK; ks += 8) {                                       \
        uint32_t af[2][4]; uint32_t bf2[4][2];                                 \
        _Pragma("unroll")                                                      \
        for (int mi = 0; mi < 2; mi++) {                                       \
            int mr = wm * 32 + mi * 16 + gid;                                  \
            af[mi][0] = __float_as_uint(AsC[mr][ks + tig]);                    \
            af[mi][1] = __float_as_uint(AsC[mr + 8][ks + tig]);                \
            af[mi][2] = __float_as_uint(AsC[mr][ks + tig + 4]);                \
            af[mi][3] = __float_as_uint(AsC[mr + 8][ks + tig + 4]);            \
        }                                                                      \
        _Pragma("unroll")                                                      \
        for (int ni = 0; ni < 4; ni++) {                                       \
            int nc = wn * 32 + ni * 8 + gid;                                   \
            bf2[ni][0] = __float_as_uint(BsC[ks + tig][nc]);                   \
            bf2[ni][1] = __float_as_uint(BsC[ks + tig + 4][nc]);               \
        }                                                                      \
        _Pragma("unroll")                                                      \
        for (int mi = 0; mi < 2; mi++)                                         \
            _Pragma("unroll")                                                  \
            for (int ni = 0; ni < 4; ni++)                                     \
                asm volatile(                                                  \
                    "mma.sync.aligned.m16n8k8.row.col.f32.tf32.tf32.f32 "      \
                    "{%0,%1,%2,%3}, {%4,%5,%6,%7}, {%8,%9}, {%0,%1,%2,%3};\n"  \
                    : "+f"(acc[mi][ni][0]), "+f"(acc[mi][ni][1]),              \
                      "+f"(acc[mi][ni][2]), "+f"(acc[mi][ni][3])               \
                    : "r"(af[mi][0]), "r"(af[mi][1]),                          \
                      "r"(af[mi][2]), "r"(af[mi][3]),                          \
                      "r"(bf2[ni][0]), "r"(bf2[ni][1]));                       \
    }

// ---------------------------------------------------------------------------
// QKV projection. Epilogue rounds outputs to tf32 so downstream cp.async
// consumers (scores/pv) see exactly the values the old staging cvt produced.
// ---------------------------------------------------------------------------
__global__ void qkv_kernel(const float* __restrict__ x,
                           const float* __restrict__ Wq, const float* __restrict__ bq,
                           const float* __restrict__ Wk, const float* __restrict__ bk,
                           const float* __restrict__ Wv, const float* __restrict__ bv)
{
    __shared__ float As[2][BK][BM + PADF];
    __shared__ float Bs[2][BK][BN + PADF];

    const int j   = blockIdx.z;
    const int mat = j >> 1;
    const int n   = j & 1;
    const int o0  = blockIdx.x * BN;
    const int m0  = blockIdx.y * BM;

    const float* W    = (mat == 0) ? Wq : (mat == 1) ? Wk : Wv;
    const float* bias = (mat == 0) ? bq : (mat == 1) ? bk : bv;
    float* out        = (mat == 0) ? g_Q : (mat == 1) ? g_K : g_V;

    const float* A  = x + (size_t)m0 * Ee + n * Hh;              // lda = Ee
    const float* Bm = W + (size_t)n * Hh * Hh + (size_t)o0 * Hh; // ldb = Hh

    const int tid = threadIdx.x;
    const int lane = tid & 31;
    const int wm = (tid >> 5) >> 1, wn = (tid >> 5) & 1;
    const int gid = lane >> 2, tig = lane & 3;
    const int lr = tid >> 2, lk = (tid & 3) * 4;

    float acc[2][4][4] = {};

    {
        float4 a0 = *(const float4*)(A + (size_t)lr * Ee + lk);
        float4 a1 = *(const float4*)(A + (size_t)(lr + 64) * Ee + lk);
        float4 b0 = *(const float4*)(Bm + (size_t)lr * Hh + lk);
        As[0][lk+0][lr] = f2tf32(a0.x); As[0][lk+1][lr] = f2tf32(a0.y); As[0][lk+2][lr] = f2tf32(a0.z); As[0][lk+3][lr] = f2tf32(a0.w);
        As[0][lk+0][lr+64] = f2tf32(a1.x); As[0][lk+1][lr+64] = f2tf32(a1.y); As[0][lk+2][lr+64] = f2tf32(a1.z); As[0][lk+3][lr+64] = f2tf32(a1.w);
        Bs[0][lk+0][lr] = f2tf32(b0.x); Bs[0][lk+1][lr] = f2tf32(b0.y); Bs[0][lk+2][lr] = f2tf32(b0.z); Bs[0][lk+3][lr] = f2tf32(b0.w);
    }
    __syncthreads();

    const int T = Hh / BK;
    int cur = 0;
    for (int t = 0; t < T; t++) {
        float4 pa0, pa1, pb;
        if (t + 1 < T) {
            int k0 = (t + 1) * BK;
            pa0 = *(const float4*)(A + (size_t)lr * Ee + k0 + lk);
            pa1 = *(const float4*)(A + (size_t)(lr + 64) * Ee + k0 + lk);
            pb  = *(const float4*)(Bm + (size_t)lr * Hh + k0 + lk);
        }
        MMA_TILE(As[cur], Bs[cur]);
        if (t + 1 < T) {
            int nx = cur ^ 1;
            As[nx][lk+0][lr] = f2tf32(pa0.x); As[nx][lk+1][lr] = f2tf32(pa0.y); As[nx][lk+2][lr] = f2tf32(pa0.z); As[nx][lk+3][lr] = f2tf32(pa0.w);
            As[nx][lk+0][lr+64] = f2tf32(pa1.x); As[nx][lk+1][lr+64] = f2tf32(pa1.y); As[nx][lk+2][lr+64] = f2tf32(pa1.z); As[nx][lk+3][lr+64] = f2tf32(pa1.w);
            Bs[nx][lk+0][lr] = f2tf32(pb.x); Bs[nx][lk+1][lr] = f2tf32(pb.y); Bs[nx][lk+2][lr] = f2tf32(pb.z); Bs[nx][lk+3][lr] = f2tf32(pb.w);
            __syncthreads();
            cur = nx;
        }
    }

#pragma unroll
    for (int mi = 0; mi < 2; mi++) {
#pragma unroll
        for (int half = 0; half < 2; half++) {
            int m = m0 + wm * 32 + mi * 16 + gid + half * 8;
            int b = m / Ss, s = m % Ss;
            size_t rowbase = ((size_t)(b * 2 + n) * Ss + s) * Hh;
#pragma unroll
            for (int ni = 0; ni < 4; ni++) {
                int o = o0 + wn * 32 + ni * 8 + tig * 2;
                float c0 = f2tf32(acc[mi][ni][half * 2 + 0] + bias[n * Hh + o]);
                float c1 = f2tf32(acc[mi][ni][half * 2 + 1] + bias[n * Hh + o + 1]);
                *(float2*)&out[rowbase + o] = make_float2(c0, c1);
            }
        }
    }
}

// ---------------------------------------------------------------------------
// scores: cp.async 3-stage pipeline; blocks above diagonal skipped;
// longest-first CTA order. Inputs g_Q/g_K are pre-rounded to tf32.
// ---------------------------------------------------------------------------
__global__ void scores_kernel(const int* __restrict__ maskedp)
{
    __shared__ __align__(16) float As[NSTG][BM][BK + PADK];  // 30720 B
    __shared__ __align__(16) float Bs[NSTG][BN][BK + PADK];  // 15360 B

    const int g  = blockIdx.z;
    const int t0 = blockIdx.x * BN;
    const int s0 = (gridDim.y - 1 - blockIdx.y) * BM;   // reversed order
    const int masked = *maskedp;

    if (masked && t0 >= s0 + BM) return;

    float* out = g_Sc + (size_t)g * Ss * Ss;
    const float* A  = g_Q + (size_t)g * Ss * Hh + (size_t)s0 * Hh;
    const float* Bm = g_K + (size_t)g * Ss * Hh + (size_t)t0 * Hh;

    const int tid = threadIdx.x;
    const int lane = tid & 31;
    const int wm = (tid >> 5) >> 1, wn = (tid >> 5) & 1;
    const int gid = lane >> 2, tig = lane & 3;

    // cp.async loader indices
    const int arow = tid >> 1, acol = (tid & 1) * 8;   // A: 2 threads/row, 8 floats each
    const int brow = tid >> 2, bcol = (tid & 3) * 4;   // B: 4 threads/row, 4 floats each

    const int T = Hh / BK;   // 32

#define SC_ISSUE(t)                                                            \
    do { if ((t) < T) { int k0 = (t) * BK; int st = (t) % NSTG;                \
        cp16(&As[st][arow][acol],     A  + (size_t)arow * Hh + k0 + acol);     \
        cp16(&As[st][arow][acol + 4], A  + (size_t)arow * Hh + k0 + acol + 4); \
        cp16(&Bs[st][brow][bcol],     Bm + (size_t)brow * Hh + k0 + bcol);     \
    } cp_commit(); } while (0)

    SC_ISSUE(0);
    SC_ISSUE(1);

    float acc[2][4][4] = {};

    for (int t = 0; t < T; t++) {
        cp_wait_1();
        __syncthreads();
        SC_ISSUE(t + NSTG - 1);
        const int st = t % NSTG;
        MMA_KK(As[st], Bs[st]);
    }
#undef SC_ISSUE

    const float scale = 0.044194173824159216f;  // 1/sqrt(512)
#pragma unroll
    for (int mi = 0; mi < 2; mi++) {
#pragma unroll
        for (int half = 0; half < 2; half++) {
            int s = s0 + wm * 32 + mi * 16 + gid + half * 8;
#pragma unroll
            for (int ni = 0; ni < 4; ni++) {
                int tt = t0 + wn * 32 + ni * 8 + tig * 2;
                float c0 = acc[mi][ni][half * 2 + 0] * scale;
                float c1 = acc[mi][ni][half * 2 + 1] * scale;
                if (masked && tt > s)     c0 = -3.0e38f;
                if (masked && tt + 1 > s) c1 = -3.0e38f;
                *(float2*)&out[(size_t)s * Ss + tt] = make_float2(c0, c1);
            }
        }
    }
}

// ---------------------------------------------------------------------------
// Row softmax (float4-vectorized, longest rows first). Final normalize rounds
// P to tf32 so pv's cp.async sees exactly the old staging-cvt values.
// ---------------------------------------------------------------------------
__global__ void softmax_kernel(const int* __restrict__ maskedp)
{
    const int row0 = gridDim.x - 1 - blockIdx.x;
    const int s = row0 & (Ss - 1);
    const int limit = (*maskedp) ? (((s >> 7) + 1) << 7) : Ss;
    const int nvec = limit >> 2;

    float4* r4 = (float4*)(g_Sc + (size_t)row0 * Ss);
    __shared__ float red[8];
    const int tid = threadIdx.x;
    const int lane = tid & 31, warp = tid >> 5;

    float m = -3.4e38f;
    for (int i = tid; i < nvec; i += 256) {
        float4 v = r4[i];
        m = fmaxf(m, fmaxf(fmaxf(v.x, v.y), fmaxf(v.z, v.w)));
    }
#pragma unroll
    for (int off = 16; off > 0; off >>= 1)
        m = fmaxf(m, __shfl_xor_sync(0xFFFFFFFFu, m, off));
    if (lane == 0) red[warp] = m;
    __syncthreads();
    if (warp == 0) {
        float v = (lane < 8) ? red[lane] : -3.4e38f;
#pragma unroll
        for (int off = 4; off > 0; off >>= 1)
            v = fmaxf(v, __shfl_xor_sync(0xFFFFFFFFu, v, off));
        if (lane == 0) red[0] = v;
    }
    __syncthreads();
    m = red[0];
    __syncthreads();

    float sum = 0.f;
    for (int i = tid; i < nvec; i += 256) {
        float4 v = r4[i];
        v.x = __expf(v.x - m); v.y = __expf(v.y - m);
        v.z = __expf(v.z - m); v.w = __expf(v.w - m);
        r4[i] = v;
        sum += (v.x + v.y) + (v.z + v.w);
    }
#pragma unroll
    for (int off = 16; off > 0; off >>= 1)
        sum += __shfl_xor_sync(0xFFFFFFFFu, sum, off);
    if (lane == 0) red[warp] = sum;
    __syncthreads();
    if (warp == 0) {
        float v = (lane < 8) ? red[lane] : 0.f;
#pragma unroll
        for (int off = 4; off > 0; off >>= 1)
            v += __shfl_xor_sync(0xFFFFFFFFu, v, off);
        if (lane == 0) red[0] = v;
    }
    __syncthreads();
    float inv = 1.0f / red[0];
    for (int i = tid; i < nvec; i += 256) {
        float4 v = r4[i];
        v.x = f2tf32(v.x * inv); v.y = f2tf32(v.y * inv);
        v.z = f2tf32(v.z * inv); v.w = f2tf32(v.w * inv);
        r4[i] = v;
    }
}

// ---------------------------------------------------------------------------
// PV: cp.async 3-stage pipeline; causal K-limit; longest-first CTA order.
// Inputs g_Sc (P) and g_V are pre-rounded to tf32.
// ---------------------------------------------------------------------------
__global__ void pv_kernel(const int* __restrict__ maskedp)
{
    __shared__ __align__(16) float As[NSTG][BM][BK + PADK];  // 30720 B
    __shared__ __align__(16) float Bs[NSTG][BK][BN + PADF];  // 13056 B

    const int g  = blockIdx.z;
    const int h0 = blockIdx.x * BN;
    const int s0 = (gridDim.y - 1 - blockIdx.y) * BM;   // reversed order
    const int tid = threadIdx.x;

    const float* A  = g_Sc + (size_t)g * Ss * Ss + (size_t)s0 * Ss;  // lda = Ss
    const float* Bm = g_V + (size_t)g * Ss * Hh;                      // ldb = Hh

    const int kmax = (*maskedp) ? (s0 + BM) : Ss;
    const int T = kmax / BK;   // 8..128

    const int lane = tid & 31;
    const int wm = (tid >> 5) >> 1, wn = (tid >> 5) & 1;
    const int gid = lane >> 2, tig = lane & 3;

    const int arow = tid >> 1, acol = (tid & 1) * 8;    // A loader
    const int brow = tid >> 4, bcol = (tid & 15) * 4;   // B loader (16 rows x 64)

#define PV_ISSUE(t)                                                            \
    do { if ((t) < T) { int k0 = (t) * BK; int st = (t) % NSTG;                \
        cp16(&As[st][arow][acol],     A + (size_t)arow * Ss + k0 + acol);      \
        cp16(&As[st][arow][acol + 4], A + (size_t)arow * Ss + k0 + acol + 4);  \
        cp16(&Bs[st][brow][bcol],     Bm + (size_t)(k0 + brow) * Hh + h0 + bcol); \
    } cp_commit(); } while (0)

    PV_ISSUE(0);
    PV_ISSUE(1);

    float acc[2][4][4] = {};

    for (int t = 0; t < T; t++) {
        cp_wait_1();
        __syncthreads();
        PV_ISSUE(t + NSTG - 1);
        const int st = t % NSTG;
        MMA_KN(As[st], Bs[st]);
    }
#undef PV_ISSUE

    const int b = g >> 1, n = g & 1;
#pragma unroll
    for (int mi = 0; mi < 2; mi++) {
#pragma unroll
        for (int half = 0; half < 2; half++) {
            int s = s0 + wm * 32 + mi * 16 + gid + half * 8;
            size_t rowbase = ((size_t)b * Ss + s) * Ee + n * Hh;
#pragma unroll
            for (int ni = 0; ni < 4; ni++) {
                int h = h0 + wn * 32 + ni * 8 + tig * 2;
                *(float2*)&g_O[rowbase + h] =
                    make_float2(acc[mi][ni][half * 2 + 0], acc[mi][ni][half * 2 + 1]);
            }
        }
    }
}

// ---------------------------------------------------------------------------
// Final projection (NT) + bias (unchanged staging engine)
// ---------------------------------------------------------------------------
__global__ void final_kernel(const float* __restrict__ Wf,
                             const float* __restrict__ bf,
                             float* __restrict__ y)
{
    __shared__ float As[2][BK][BM + PADF];
    __shared__ float Bs[2][BK][BN + PADF];

    const int o0 = blockIdx.x * BN;
    const int m0 = blockIdx.y * BM;
    const int tid = threadIdx.x;

    const float* A  = g_O + (size_t)m0 * Ee;   // lda = Ee
    const float* Bm = Wf + (size_t)o0 * Ee;    // ldb = Ee

    const int lane = tid & 31;
    const int wm = (tid >> 5) >> 1, wn = (tid >> 5) & 1;
    const int gid = lane >> 2, tig = lane & 3;
    const int lr = tid >> 2, lk = (tid & 3) * 4;

    float acc[2][4][4] = {};

    {
        float4 a0 = *(const float4*)(A + (size_t)lr * Ee + lk);
        float4 a1 = *(const float4*)(A + (size_t)(lr + 64) * Ee + lk);
        float4 b0 = *(const float4*)(Bm + (size_t)lr * Ee + lk);
        As[0][lk+0][lr] = f2tf32(a0.x); As[0][lk+1][lr] = f2tf32(a0.y); As[0][lk+2][lr] = f2tf32(a0.z); As[0][lk+3][lr] = f2tf32(a0.w);
        As[0][lk+0][lr+64] = f2tf32(a1.x); As[0][lk+1][lr+64] = f2tf32(a1.y); As[0][lk+2][lr+64] = f2tf32(a1.z); As[0][lk+3][lr+64] = f2tf32(a1.w);
        Bs[0][lk+0][lr] = f2tf32(b0.x); Bs[0][lk+1][lr] = f2tf32(b0.y); Bs[0][lk+2][lr] = f2tf32(b0.z); Bs[0][lk+3][lr] = f2tf32(b0.w);
    }
    __syncthreads();

    const int T = Ee / BK;
    int cur = 0;
    for (int t = 0; t < T; t++) {
        float4 pa0, pa1, pb;
        if (t + 1 < T) {
            int k0 = (t + 1) * BK;
            pa0 = *(const float4*)(A + (size_t)lr * Ee + k0 + lk);
            pa1 = *(const float4*)(A + (size_t)(lr + 64) * Ee + k0 + lk);
            pb  = *(const float4*)(Bm + (size_t)lr * Ee + k0 + lk);
        }
        MMA_TILE(As[cur], Bs[cur]);
        if (t + 1 < T) {
            int nx = cur ^ 1;
            As[nx][lk+0][lr] = f2tf32(pa0.x); As[nx][lk+1][lr] = f2tf32(pa0.y); As[nx][lk+2][lr] = f2tf32(pa0.z); As[nx][lk+3][lr] = f2tf32(pa0.w);
            As[nx][lk+0][lr+64] = f2tf32(pa1.x); As[nx][lk+1][lr+64] = f2tf32(pa1.y); As[nx][lk+2][lr+64] = f2tf32(pa1.z); As[nx][lk+3][lr+64] = f2tf32(pa1.w);
            Bs[nx][lk+0][lr] = f2tf32(pb.x); Bs[nx][lk+1][lr] = f2tf32(pb.y); Bs[nx][lk+2][lr] = f2tf32(pb.z); Bs[nx][lk+3][lr] = f2tf32(pb.w);
            __syncthreads();
            cur = nx;
        }
    }

#pragma unroll
    for (int mi = 0; mi < 2; mi++) {
#pragma unroll
        for (int half = 0; half < 2; half++) {
            int m = m0 + wm * 32 + mi * 16 + gid + half * 8;
#pragma unroll
            for (int ni = 0; ni < 4; ni++) {
                int o = o0 + wn * 32 + ni * 8 + tig * 2;
                float c0 = acc[mi][ni][half * 2 + 0] + bf[o];
                float c1 = acc[mi][ni][half * 2 + 1] + bf[o + 1];
                *(float2*)&y[(size_t)m * Ee + o] = make_float2(c0, c1);
            }
        }
    }
}

// ---------------------------------------------------------------------------
extern "C" void kernel_launch(void* const* d_in, const int* in_sizes, int n_in,
                              void* d_out, int out_size)
{
    const float* x  = (const float*)d_in[0];
    const float* Wq = (const float*)d_in[1];
    const float* bq = (const float*)d_in[2];
    const float* Wk = (const float*)d_in[3];
    const float* bk = (const float*)d_in[4];
    const float* Wv = (const float*)d_in[5];
    const float* bv = (const float*)d_in[6];
    const float* Wf = (const float*)d_in[7];
    const float* bf = (const float*)d_in[8];
    const int* masked = (const int*)d_in[9];
    float* y = (float*)d_out;

    const int M = Bb * Ss;  // 8192 tokens

    qkv_kernel<<<dim3(Hh / BN, M / BM, 6), 256>>>(x, Wq, bq, Wk, bk, Wv, bv);
    scores_kernel<<<dim3(Ss / BN, Ss / BM, NG), 256>>>(masked);
    softmax_kernel<<<NG * Ss, 256>>>(masked);
    pv_kernel<<<dim3(Hh / BN, Ss / BM, NG), 256>>>(masked);
    final_kernel<<<dim3(Ee / BN, M / BM), 256>>>(Wf, bf, y);
}

// round 17
// speedup vs baseline: 1.7779x; 1.1863x over previous
#include <cuda_runtime.h>
#include <math.h>
#include <stdint.h>

// Problem constants
#define Bb 4
#define Ss 2048
#define Ee 1024
#define Hh 512
#define NG 8          // B * 2 heads

// Tile config: 128x64 block tile, BK=16, 256 threads (8 warps: 4 M x 2 N)
#define BM 128
#define BN 64
#define BK 16
#define PADF 4        // pad for [BK][N] layouts (pv B tile)
#define PADK 4        // pad for k-contiguous [M][BK+PADK] cp.async tiles (stride 20)
#define NSTG 3        // cp.async pipeline stages

// Scratch
__device__ float g_Q[NG * Ss * Hh];
__device__ float g_K[NG * Ss * Hh];
__device__ float g_V[NG * Ss * Hh];
__device__ float g_Sc[(size_t)NG * Ss * Ss];
__device__ float g_O[Bb * Ss * Ee];

// fp32 -> tf32 (round-to-nearest)
__device__ __forceinline__ float f2tf32(float x) {
    asm("cvt.rna.tf32.f32 %0, %0;" : "+f"(x));
    return x;
}
__device__ __forceinline__ uint32_t ld_tf32(float x) {
    asm("cvt.rna.tf32.f32 %0, %0;" : "+f"(x));
    return __float_as_uint(x);
}

// cp.async helpers
__device__ __forceinline__ void cp16(void* dst, const void* src) {
    uint32_t d = (uint32_t)__cvta_generic_to_shared(dst);
    asm volatile("cp.async.cg.shared.global [%0], [%1], 16;\n" :: "r"(d), "l"(src));
}
__device__ __forceinline__ void cp_commit() {
    asm volatile("cp.async.commit_group;\n" ::: "memory");
}
__device__ __forceinline__ void cp_wait_1() {
    asm volatile("cp.async.wait_group 1;\n" ::: "memory");
}

// --- MMA, both operands k-contiguous, PRE-ROUNDED inputs (scores) ---
#define MMA_KK(AsC, BsC)                                                       \
    _Pragma("unroll")                                                          \
    for (int ks = 0; ks < BK; ks += 8) {                                       \
        uint32_t af[2][4]; uint32_t bf2[4][2];                                 \
        _Pragma("unroll")                                                      \
        for (int mi = 0; mi < 2; mi++) {                                       \
            int mr = wm * 32 + mi * 16 + gid;                                  \
            af[mi][0] = __float_as_uint(AsC[mr][ks + tig]);                    \
            af[mi][1] = __float_as_uint(AsC[mr + 8][ks + tig]);                \
            af[mi][2] = __float_as_uint(AsC[mr][ks + tig + 4]);                \
            af[mi][3] = __float_as_uint(AsC[mr + 8][ks + tig + 4]);            \
        }                                                                      \
        _Pragma("unroll")                                                      \
        for (int ni = 0; ni < 4; ni++) {                                       \
            int nc = wn * 32 + ni * 8 + gid;                                   \
            bf2[ni][0] = __float_as_uint(BsC[nc][ks + tig]);                   \
            bf2[ni][1] = __float_as_uint(BsC[nc][ks + tig + 4]);               \
        }                                                                      \
        _Pragma("unroll")                                                      \
        for (int mi = 0; mi < 2; mi++)                                         \
            _Pragma("unroll")                                                  \
            for (int ni = 0; ni < 4; ni++)                                     \
                asm volatile(                                                  \
                    "mma.sync.aligned.m16n8k8.row.col.f32.tf32.tf32.f32 "      \
                    "{%0,%1,%2,%3}, {%4,%5,%6,%7}, {%8,%9}, {%0,%1,%2,%3};\n"  \
                    : "+f"(acc[mi][ni][0]), "+f"(acc[mi][ni][1]),              \
                      "+f"(acc[mi][ni][2]), "+f"(acc[mi][ni][3])               \
                    : "r"(af[mi][0]), "r"(af[mi][1]),                          \
                      "r"(af[mi][2]), "r"(af[mi][3]),                          \
                      "r"(bf2[ni][0]), "r"(bf2[ni][1]));                       \
    }

// --- MMA_KK with fragment-load ROUNDING (qkv/final: raw fp32 in smem) ---
// cvt.rna at fragment load reproduces the old staging-time rounding bit-exactly.
#define MMA_KKR(AsC, BsC)                                                      \
    _Pragma("unroll")                                                          \
    for (int ks = 0; ks < BK; ks += 8) {                                       \
        uint32_t af[2][4]; uint32_t bf2[4][2];                                 \
        _Pragma("unroll")                                                      \
        for (int mi = 0; mi < 2; mi++) {                                       \
            int mr = wm * 32 + mi * 16 + gid;                                  \
            af[mi][0] = ld_tf32(AsC[mr][ks + tig]);                            \
            af[mi][1] = ld_tf32(AsC[mr + 8][ks + tig]);                        \
            af[mi][2] = ld_tf32(AsC[mr][ks + tig + 4]);                        \
            af[mi][3] = ld_tf32(AsC[mr + 8][ks + tig + 4]);                    \
        }                                                                      \
        _Pragma("unroll")                                                      \
        for (int ni = 0; ni < 4; ni++) {                                       \
            int nc = wn * 32 + ni * 8 + gid;                                   \
            bf2[ni][0] = ld_tf32(BsC[nc][ks + tig]);                           \
            bf2[ni][1] = ld_tf32(BsC[nc][ks + tig + 4]);                       \
        }                                                                      \
        _Pragma("unroll")                                                      \
        for (int mi = 0; mi < 2; mi++)                                         \
            _Pragma("unroll")                                                  \
            for (int ni = 0; ni < 4; ni++)                                     \
                asm volatile(                                                  \
                    "mma.sync.aligned.m16n8k8.row.col.f32.tf32.tf32.f32 "      \
                    "{%0,%1,%2,%3}, {%4,%5,%6,%7}, {%8,%9}, {%0,%1,%2,%3};\n"  \
                    : "+f"(acc[mi][ni][0]), "+f"(acc[mi][ni][1]),              \
                      "+f"(acc[mi][ni][2]), "+f"(acc[mi][ni][3])               \
                    : "r"(af[mi][0]), "r"(af[mi][1]),                          \
                      "r"(af[mi][2]), "r"(af[mi][3]),                          \
                      "r"(bf2[ni][0]), "r"(bf2[ni][1]));                       \
    }

// --- MMA, A k-contiguous, B n-contiguous, PRE-ROUNDED inputs (pv) ---
#define MMA_KN(AsC, BsC)                                                       \
    _Pragma("unroll")                                                          \
    for (int ks = 0; ks < BK; ks += 8) {                                       \
        uint32_t af[2][4]; uint32_t bf2[4][2];                                 \
        _Pragma("unroll")                                                      \
        for (int mi = 0; mi < 2; mi++) {                                       \
            int mr = wm * 32 + mi * 16 + gid;                                  \
            af[mi][0] = __float_as_uint(AsC[mr][ks + tig]);                    \
            af[mi][1] = __float_as_uint(AsC[mr + 8][ks + tig]);                \
            af[mi][2] = __float_as_uint(AsC[mr][ks + tig + 4]);                \
            af[mi][3] = __float_as_uint(AsC[mr + 8][ks + tig + 4]);            \
        }                                                                      \
        _Pragma("unroll")                                                      \
        for (int ni = 0; ni < 4; ni++) {                                       \
            int nc = wn * 32 + ni * 8 + gid;                                   \
            bf2[ni][0] = __float_as_uint(BsC[ks + tig][nc]);                   \
            bf2[ni][1] = __float_as_uint(BsC[ks + tig + 4][nc]);               \
        }                                                                      \
        _Pragma("unroll")                                                      \
        for (int mi = 0; mi < 2; mi++)                                         \
            _Pragma("unroll")                                                  \
            for (int ni = 0; ni < 4; ni++)                                     \
                asm volatile(                                                  \
                    "mma.sync.aligned.m16n8k8.row.col.f32.tf32.tf32.f32 "      \
                    "{%0,%1,%2,%3}, {%4,%5,%6,%7}, {%8,%9}, {%0,%1,%2,%3};\n"  \
                    : "+f"(acc[mi][ni][0]), "+f"(acc[mi][ni][1]),              \
                      "+f"(acc[mi][ni][2]), "+f"(acc[mi][ni][3])               \
                    : "r"(af[mi][0]), "r"(af[mi][1]),                          \
                      "r"(af[mi][2]), "r"(af[mi][3]),                          \
                      "r"(bf2[ni][0]), "r"(bf2[ni][1]));                       \
    }

// ---------------------------------------------------------------------------
// QKV projection: cp.async pipeline, MMA_KKR (round-to-nearest at frag load).
// Epilogue rounds outputs to tf32 for downstream cp.async consumers.
// ---------------------------------------------------------------------------
__global__ void qkv_kernel(const float* __restrict__ x,
                           const float* __restrict__ Wq, const float* __restrict__ bq,
                           const float* __restrict__ Wk, const float* __restrict__ bk,
                           const float* __restrict__ Wv, const float* __restrict__ bv)
{
    __shared__ __align__(16) float As[NSTG][BM][BK + PADK];
    __shared__ __align__(16) float Bs[NSTG][BN][BK + PADK];

    const int j   = blockIdx.z;
    const int mat = j >> 1;
    const int n   = j & 1;
    const int o0  = blockIdx.x * BN;
    const int m0  = blockIdx.y * BM;

    const float* W    = (mat == 0) ? Wq : (mat == 1) ? Wk : Wv;
    const float* bias = (mat == 0) ? bq : (mat == 1) ? bk : bv;
    float* out        = (mat == 0) ? g_Q : (mat == 1) ? g_K : g_V;

    const float* A  = x + (size_t)m0 * Ee + n * Hh;              // lda = Ee
    const float* Bm = W + (size_t)n * Hh * Hh + (size_t)o0 * Hh; // ldb = Hh

    const int tid = threadIdx.x;
    const int lane = tid & 31;
    const int wm = (tid >> 5) >> 1, wn = (tid >> 5) & 1;
    const int gid = lane >> 2, tig = lane & 3;

    const int arow = tid >> 1, acol = (tid & 1) * 8;
    const int brow = tid >> 2, bcol = (tid & 3) * 4;

    const int T = Hh / BK;   // 32

#define QK_ISSUE(t)                                                            \
    do { if ((t) < T) { int k0 = (t) * BK; int st = (t) % NSTG;                \
        cp16(&As[st][arow][acol],     A  + (size_t)arow * Ee + k0 + acol);     \
        cp16(&As[st][arow][acol + 4], A  + (size_t)arow * Ee + k0 + acol + 4); \
        cp16(&Bs[st][brow][bcol],     Bm + (size_t)brow * Hh + k0 + bcol);     \
    } cp_commit(); } while (0)

    QK_ISSUE(0);
    QK_ISSUE(1);

    float acc[2][4][4] = {};

    for (int t = 0; t < T; t++) {
        cp_wait_1();
        __syncthreads();
        QK_ISSUE(t + NSTG - 1);
        const int st = t % NSTG;
        MMA_KKR(As[st], Bs[st]);
    }
#undef QK_ISSUE

#pragma unroll
    for (int mi = 0; mi < 2; mi++) {
#pragma unroll
        for (int half = 0; half < 2; half++) {
            int m = m0 + wm * 32 + mi * 16 + gid + half * 8;
            int b = m / Ss, s = m % Ss;
            size_t rowbase = ((size_t)(b * 2 + n) * Ss + s) * Hh;
#pragma unroll
            for (int ni = 0; ni < 4; ni++) {
                int o = o0 + wn * 32 + ni * 8 + tig * 2;
                float c0 = f2tf32(acc[mi][ni][half * 2 + 0] + bias[n * Hh + o]);
                float c1 = f2tf32(acc[mi][ni][half * 2 + 1] + bias[n * Hh + o + 1]);
                *(float2*)&out[rowbase + o] = make_float2(c0, c1);
            }
        }
    }
}

// ---------------------------------------------------------------------------
// scores: cp.async pipeline; diag skip; longest-first. Inputs pre-rounded.
// ---------------------------------------------------------------------------
__global__ void scores_kernel(const int* __restrict__ maskedp)
{
    __shared__ __align__(16) float As[NSTG][BM][BK + PADK];
    __shared__ __align__(16) float Bs[NSTG][BN][BK + PADK];

    const int g  = blockIdx.z;
    const int t0 = blockIdx.x * BN;
    const int s0 = (gridDim.y - 1 - blockIdx.y) * BM;   // reversed order
    const int masked = *maskedp;

    if (masked && t0 >= s0 + BM) return;

    float* out = g_Sc + (size_t)g * Ss * Ss;
    const float* A  = g_Q + (size_t)g * Ss * Hh + (size_t)s0 * Hh;
    const float* Bm = g_K + (size_t)g * Ss * Hh + (size_t)t0 * Hh;

    const int tid = threadIdx.x;
    const int lane = tid & 31;
    const int wm = (tid >> 5) >> 1, wn = (tid >> 5) & 1;
    const int gid = lane >> 2, tig = lane & 3;

    const int arow = tid >> 1, acol = (tid & 1) * 8;
    const int brow = tid >> 2, bcol = (tid & 3) * 4;

    const int T = Hh / BK;   // 32

#define SC_ISSUE(t)                                                            \
    do { if ((t) < T) { int k0 = (t) * BK; int st = (t) % NSTG;                \
        cp16(&As[st][arow][acol],     A  + (size_t)arow * Hh + k0 + acol);     \
        cp16(&As[st][arow][acol + 4], A  + (size_t)arow * Hh + k0 + acol + 4); \
        cp16(&Bs[st][brow][bcol],     Bm + (size_t)brow * Hh + k0 + bcol);     \
    } cp_commit(); } while (0)

    SC_ISSUE(0);
    SC_ISSUE(1);

    float acc[2][4][4] = {};

    for (int t = 0; t < T; t++) {
        cp_wait_1();
        __syncthreads();
        SC_ISSUE(t + NSTG - 1);
        const int st = t % NSTG;
        MMA_KK(As[st], Bs[st]);
    }
#undef SC_ISSUE

    const float scale = 0.044194173824159216f;  // 1/sqrt(512)
#pragma unroll
    for (int mi = 0; mi < 2; mi++) {
#pragma unroll
        for (int half = 0; half < 2; half++) {
            int s = s0 + wm * 32 + mi * 16 + gid + half * 8;
#pragma unroll
            for (int ni = 0; ni < 4; ni++) {
                int tt = t0 + wn * 32 + ni * 8 + tig * 2;
                float c0 = acc[mi][ni][half * 2 + 0] * scale;
                float c1 = acc[mi][ni][half * 2 + 1] * scale;
                if (masked && tt > s)     c0 = -3.0e38f;
                if (masked && tt + 1 > s) c1 = -3.0e38f;
                *(float2*)&out[(size_t)s * Ss + tt] = make_float2(c0, c1);
            }
        }
    }
}

// ---------------------------------------------------------------------------
// Row softmax (float4, longest rows first). Normalize rounds P to tf32.
// ---------------------------------------------------------------------------
__global__ void softmax_kernel(const int* __restrict__ maskedp)
{
    const int row0 = gridDim.x - 1 - blockIdx.x;
    const int s = row0 & (Ss - 1);
    const int limit = (*maskedp) ? (((s >> 7) + 1) << 7) : Ss;
    const int nvec = limit >> 2;

    float4* r4 = (float4*)(g_Sc + (size_t)row0 * Ss);
    __shared__ float red[8];
    const int tid = threadIdx.x;
    const int lane = tid & 31, warp = tid >> 5;

    float m = -3.4e38f;
    for (int i = tid; i < nvec; i += 256) {
        float4 v = r4[i];
        m = fmaxf(m, fmaxf(fmaxf(v.x, v.y), fmaxf(v.z, v.w)));
    }
#pragma unroll
    for (int off = 16; off > 0; off >>= 1)
        m = fmaxf(m, __shfl_xor_sync(0xFFFFFFFFu, m, off));
    if (lane == 0) red[warp] = m;
    __syncthreads();
    if (warp == 0) {
        float v = (lane < 8) ? red[lane] : -3.4e38f;
#pragma unroll
        for (int off = 4; off > 0; off >>= 1)
            v = fmaxf(v, __shfl_xor_sync(0xFFFFFFFFu, v, off));
        if (lane == 0) red[0] = v;
    }
    __syncthreads();
    m = red[0];
    __syncthreads();

    float sum = 0.f;
    for (int i = tid; i < nvec; i += 256) {
        float4 v = r4[i];
        v.x = __expf(v.x - m); v.y = __expf(v.y - m);
        v.z = __expf(v.z - m); v.w = __expf(v.w - m);
        r4[i] = v;
        sum += (v.x + v.y) + (v.z + v.w);
    }
#pragma unroll
    for (int off = 16; off > 0; off >>= 1)
        sum += __shfl_xor_sync(0xFFFFFFFFu, sum, off);
    if (lane == 0) red[warp] = sum;
    __syncthreads();
    if (warp == 0) {
        float v = (lane < 8) ? red[lane] : 0.f;
#pragma unroll
        for (int off = 4; off > 0; off >>= 1)
            v += __shfl_xor_sync(0xFFFFFFFFu, v, off);
        if (lane == 0) red[0] = v;
    }
    __syncthreads();
    float inv = 1.0f / red[0];
    for (int i = tid; i < nvec; i += 256) {
        float4 v = r4[i];
        v.x = f2tf32(v.x * inv); v.y = f2tf32(v.y * inv);
        v.z = f2tf32(v.z * inv); v.w = f2tf32(v.w * inv);
        r4[i] = v;
    }
}

// ---------------------------------------------------------------------------
// PV: cp.async pipeline; causal K-limit; longest-first. Inputs pre-rounded.
// ---------------------------------------------------------------------------
__global__ void pv_kernel(const int* __restrict__ maskedp)
{
    __shared__ __align__(16) float As[NSTG][BM][BK + PADK];
    __shared__ __align__(16) float Bs[NSTG][BK][BN + PADF];

    const int g  = blockIdx.z;
    const int h0 = blockIdx.x * BN;
    const int s0 = (gridDim.y - 1 - blockIdx.y) * BM;   // reversed order
    const int tid = threadIdx.x;

    const float* A  = g_Sc + (size_t)g * Ss * Ss + (size_t)s0 * Ss;  // lda = Ss
    const float* Bm = g_V + (size_t)g * Ss * Hh;                      // ldb = Hh

    const int kmax = (*maskedp) ? (s0 + BM) : Ss;
    const int T = kmax / BK;

    const int lane = tid & 31;
    const int wm = (tid >> 5) >> 1, wn = (tid >> 5) & 1;
    const int gid = lane >> 2, tig = lane & 3;

    const int arow = tid >> 1, acol = (tid & 1) * 8;
    const int brow = tid >> 4, bcol = (tid & 15) * 4;

#define PV_ISSUE(t)                                                            \
    do { if ((t) < T) { int k0 = (t) * BK; int st = (t) % NSTG;                \
        cp16(&As[st][arow][acol],     A + (size_t)arow * Ss + k0 + acol);      \
        cp16(&As[st][arow][acol + 4], A + (size_t)arow * Ss + k0 + acol + 4);  \
        cp16(&Bs[st][brow][bcol],     Bm + (size_t)(k0 + brow) * Hh + h0 + bcol); \
    } cp_commit(); } while (0)

    PV_ISSUE(0);
    PV_ISSUE(1);

    float acc[2][4][4] = {};

    for (int t = 0; t < T; t++) {
        cp_wait_1();
        __syncthreads();
        PV_ISSUE(t + NSTG - 1);
        const int st = t % NSTG;
        MMA_KN(As[st], Bs[st]);
    }
#undef PV_ISSUE

    const int b = g >> 1, n = g & 1;
#pragma unroll
    for (int mi = 0; mi < 2; mi++) {
#pragma unroll
        for (int half = 0; half < 2; half++) {
            int s = s0 + wm * 32 + mi * 16 + gid + half * 8;
            size_t rowbase = ((size_t)b * Ss + s) * Ee + n * Hh;
#pragma unroll
            for (int ni = 0; ni < 4; ni++) {
                int h = h0 + wn * 32 + ni * 8 + tig * 2;
                *(float2*)&g_O[rowbase + h] =
                    make_float2(acc[mi][ni][half * 2 + 0], acc[mi][ni][half * 2 + 1]);
            }
        }
    }
}

// ---------------------------------------------------------------------------
// Final projection: cp.async pipeline, MMA_KKR (round at frag load), T=64.
// ---------------------------------------------------------------------------
__global__ void final_kernel(const float* __restrict__ Wf,
                             const float* __restrict__ bf,
                             float* __restrict__ y)
{
    __shared__ __align__(16) float As[NSTG][BM][BK + PADK];
    __shared__ __align__(16) float Bs[NSTG][BN][BK + PADK];

    const int o0 = blockIdx.x * BN;
    const int m0 = blockIdx.y * BM;
    const int tid = threadIdx.x;

    const float* A  = g_O + (size_t)m0 * Ee;   // lda = Ee
    const float* Bm = Wf + (size_t)o0 * Ee;    // ldb = Ee

    const int lane = tid & 31;
    const int wm = (tid >> 5) >> 1, wn = (tid >> 5) & 1;
    const int gid = lane >> 2, tig = lane & 3;

    const int arow = tid >> 1, acol = (tid & 1) * 8;
    const int brow = tid >> 2, bcol = (tid & 3) * 4;

    const int T = Ee / BK;   // 64

#define FN_ISSUE(t)                                                            \
    do { if ((t) < T) { int k0 = (t) * BK; int st = (t) % NSTG;                \
        cp16(&As[st][arow][acol],     A  + (size_t)arow * Ee + k0 + acol);     \
        cp16(&As[st][arow][acol + 4], A  + (size_t)arow * Ee + k0 + acol + 4); \
        cp16(&Bs[st][brow][bcol],     Bm + (size_t)brow * Ee + k0 + bcol);     \
    } cp_commit(); } while (0)

    FN_ISSUE(0);
    FN_ISSUE(1);

    float acc[2][4][4] = {};

    for (int t = 0; t < T; t++) {
        cp_wait_1();
        __syncthreads();
        FN_ISSUE(t + NSTG - 1);
        const int st = t % NSTG;
        MMA_KKR(As[st], Bs[st]);
    }
#undef FN_ISSUE

#pragma unroll
    for (int mi = 0; mi < 2; mi++) {
#pragma unroll
        for (int half = 0; half < 2; half++) {
            int m = m0 + wm * 32 + mi * 16 + gid + half * 8;
#pragma unroll
            for (int ni = 0; ni < 4; ni++) {
                int o = o0 + wn * 32 + ni * 8 + tig * 2;
                float c0 = acc[mi][ni][half * 2 + 0] + bf[o];
                float c1 = acc[mi][ni][half * 2 + 1] + bf[o + 1];
                *(float2*)&y[(size_t)m * Ee + o] = make_float2(c0, c1);
            }
        }
    }
}

// ---------------------------------------------------------------------------
extern "C" void kernel_launch(void* const* d_in, const int* in_sizes, int n_in,
                              void* d_out, int out_size)
{
    const float* x  = (const float*)d_in[0];
    const float* Wq = (const float*)d_in[1];
    const float* bq = (const float*)d_in[2];
    const float* Wk = (const float*)d_in[3];
    const float* bk = (const float*)d_in[4];
    const float* Wv = (const float*)d_in[5];
    const float* bv = (const float*)d_in[6];
    const float* Wf = (const float*)d_in[7];
    const float* bf = (const float*)d_in[8];
    const int* masked = (const int*)d_in[9];
    float* y = (float*)d_out;

    const int M = Bb * Ss;  // 8192 tokens

    qkv_kernel<<<dim3(Hh / BN, M / BM, 6), 256>>>(x, Wq, bq, Wk, bk, Wv, bv);
    scores_kernel<<<dim3(Ss / BN, Ss / BM, NG), 256>>>(masked);
    softmax_kernel<<<NG * Ss, 256>>>(masked);
    pv_kernel<<<dim3(Hh / BN, Ss / BM, NG), 256>>>(masked);
    final_kernel<<<dim3(Ee / BN, M / BM), 256>>>(Wf, bf, y);
}